// round 1
// baseline (speedup 1.0000x reference)
#include <cuda_runtime.h>

// Problem constants (fixed by setup_inputs): B=16, C=128, N=M=2048
#define B_  16
#define C_  128
#define N_  2048
#define TN  128      // n-tile per CTA (rows of S)
#define TM  128      // m-tile per inner loop (cols of S)
#define KB  16       // k-chunk staged in smem
#define SCALE 10.0f  // 1/TEMPERATURE

// Scratch (no cudaMalloc allowed)
__device__ float g_pos[B_ * N_];       // per-(b,n) positive dot
__device__ float g_partial[256];       // per-CTA loss partial sums

// ---------------------------------------------------------------------------
// Kernel 1: l_positive[b,n] = sum_c q[b,c,n]*p[b,c,n]
// Threads map to (b,n); loads are coalesced across n within a warp.
// ---------------------------------------------------------------------------
__global__ void pos_kernel(const float* __restrict__ q,
                           const float* __restrict__ p) {
    int idx = blockIdx.x * blockDim.x + threadIdx.x;   // 0 .. B*N-1
    int b = idx >> 11;            // N_ = 2048 = 2^11
    int n = idx & (N_ - 1);
    const float* qp = q + (size_t)b * C_ * N_ + n;
    const float* pp = p + (size_t)b * C_ * N_ + n;
    float s = 0.f;
#pragma unroll 8
    for (int c = 0; c < C_; c++)
        s = fmaf(qp[(size_t)c * N_], pp[(size_t)c * N_], s);
    g_pos[idx] = s;
}

// ---------------------------------------------------------------------------
// Kernel 2: fused GEMM + online logsumexp.
// CTA (bx, by=b): rows n0..n0+127. Loops m over 2048 in 128-wide tiles.
// 256 threads, 8x8 register tile each. S never hits memory.
// ---------------------------------------------------------------------------
__global__ __launch_bounds__(256, 2)
void main_kernel(const float* __restrict__ q,
                 const float* __restrict__ neg) {
    __shared__ union SM {
        struct { float A[KB][TN]; float B[KB][TM]; } g;   // 16 KB GEMM stage
        struct { float m[TN][16]; float s[TN][16]; } r;   // 16 KB reduction
    } sm;

    const int tid = threadIdx.x;
    const int tx = tid & 15;       // 16 thread-cols
    const int ty = tid >> 4;       // 16 thread-rows
    const int b  = blockIdx.y;
    const int n0 = blockIdx.x * TN;

    const float* qbase = q   + (size_t)b * C_ * N_ + n0;  // A tile base
    const float* nbase = neg + (size_t)b * C_ * N_;       // B tile base

    float rmax[8], rsum[8];
#pragma unroll
    for (int i = 0; i < 8; i++) { rmax[i] = -1e30f; rsum[i] = 0.f; }

    for (int mt = 0; mt < N_; mt += TM) {
        float acc[8][8];
#pragma unroll
        for (int i = 0; i < 8; i++)
#pragma unroll
            for (int j = 0; j < 8; j++) acc[i][j] = 0.f;

        for (int kc = 0; kc < C_; kc += KB) {
            __syncthreads();
            // Stage KB x 128 chunks of A (=Q^T tile) and B (=Neg tile).
            // 512 float4 per matrix, 2 per thread, fully coalesced.
#pragma unroll
            for (int l = 0; l < 2; l++) {
                int s4 = tid + l * 256;
                int r  = s4 >> 5;          // smem row (k within chunk)
                int c4 = (s4 & 31) << 2;   // smem col
                *(float4*)&sm.g.A[r][c4] =
                    *(const float4*)(qbase + (size_t)(kc + r) * N_ + c4);
                *(float4*)&sm.g.B[r][c4] =
                    *(const float4*)(nbase + (size_t)(kc + r) * N_ + mt + c4);
            }
            __syncthreads();

#pragma unroll
            for (int k = 0; k < KB; k++) {
                float4 a0 = *(float4*)&sm.g.A[k][ty * 8];
                float4 a1 = *(float4*)&sm.g.A[k][ty * 8 + 4];
                float4 b0 = *(float4*)&sm.g.B[k][tx * 8];
                float4 b1 = *(float4*)&sm.g.B[k][tx * 8 + 4];
                float av[8] = {a0.x, a0.y, a0.z, a0.w, a1.x, a1.y, a1.z, a1.w};
                float bv[8] = {b0.x, b0.y, b0.z, b0.w, b1.x, b1.y, b1.z, b1.w};
#pragma unroll
                for (int i = 0; i < 8; i++)
#pragma unroll
                    for (int j = 0; j < 8; j++)
                        acc[i][j] = fmaf(av[i], bv[j], acc[i][j]);
            }
        }

        // Online max / sumexp update for this m-tile (logits = dot * 10)
#pragma unroll
        for (int i = 0; i < 8; i++) {
            float m = rmax[i];
#pragma unroll
            for (int j = 0; j < 8; j++) m = fmaxf(m, acc[i][j] * SCALE);
            float s = rsum[i] * __expf(rmax[i] - m);
#pragma unroll
            for (int j = 0; j < 8; j++) s += __expf(acc[i][j] * SCALE - m);
            rmax[i] = m; rsum[i] = s;
        }
    }

    // Cross-thread combine: 16 threads (tx) share each row.
    __syncthreads();
#pragma unroll
    for (int i = 0; i < 8; i++) {
        sm.r.m[ty * 8 + i][tx] = rmax[i];
        sm.r.s[ty * 8 + i][tx] = rsum[i];
    }
    __syncthreads();

    float loss = 0.f;
    if (tid < TN) {
        float M = -1e30f;
#pragma unroll
        for (int t = 0; t < 16; t++) M = fmaxf(M, sm.r.m[tid][t]);
        float S = 0.f;
#pragma unroll
        for (int t = 0; t < 16; t++)
            S += sm.r.s[tid][t] * __expf(sm.r.m[tid][t] - M);
        // fold positive logit into the LSE (it's class 0 of the softmax)
        float lp = g_pos[b * N_ + n0 + tid] * SCALE;
        float M2 = fmaxf(M, lp);
        float S2 = S * __expf(M - M2) + __expf(lp - M2);
        loss = M2 + logf(S2) - lp;     // LSE(all logits) - logit[0]
    }

    // Deterministic block reduction of 128 loss values (others contribute 0)
    __syncthreads();
    float* red = &sm.r.m[0][0];        // 2048 floats available
    red[tid] = loss;
    __syncthreads();
    for (int off = 128; off > 0; off >>= 1) {
        if (tid < off) red[tid] += red[tid + off];
        __syncthreads();
    }
    if (tid == 0) g_partial[blockIdx.y * 16 + blockIdx.x] = red[0];
}

// ---------------------------------------------------------------------------
// Kernel 3: deterministic final reduction -> mean loss
// ---------------------------------------------------------------------------
__global__ void final_kernel(float* __restrict__ out) {
    __shared__ float red[256];
    int t = threadIdx.x;
    red[t] = g_partial[t];
    __syncthreads();
    for (int off = 128; off > 0; off >>= 1) {
        if (t < off) red[t] += red[t + off];
        __syncthreads();
    }
    if (t == 0) out[0] = red[0] / (float)(B_ * N_);
}

// ---------------------------------------------------------------------------
extern "C" void kernel_launch(void* const* d_in, const int* in_sizes, int n_in,
                              void* d_out, int out_size) {
    const float* q   = (const float*)d_in[0];  // query_feature   [B,C,N]
    const float* pos = (const float*)d_in[1];  // positive_feature[B,C,N]
    const float* neg = (const float*)d_in[2];  // negative_feature[B,C,N]
    float* out = (float*)d_out;

    pos_kernel<<<(B_ * N_) / 256, 256>>>(q, pos);
    main_kernel<<<dim3(N_ / TN, B_), 256>>>(q, neg);
    final_kernel<<<1, 256>>>(out);
}

// round 3
// speedup vs baseline: 2.8317x; 2.8317x over previous
#include <cuda_runtime.h>
#include <cstdint>

// Problem constants: B=16, C=128, N=M=2048
#define B_  16
#define C_  128
#define N_  2048
#define SCALE 10.0f

#define NTILE   128            // n rows per CTA (GEMM M)
#define MCHUNK  32             // m cols per chunk (GEMM N)
#define NCHUNKS (N_ / MCHUNK)  // 64
#define THREADS 256

// SMEM layout (floats). A-stage and B-buffers overlap in time (union).
#define ASTRIDE 132            // padded A row (128 k-rows x 132)
#define BSTRIDE 40             // padded B row -> conflict-free fragment LDS
#define BBUF    (128 * BSTRIDE)        // 5120 floats per buffer
#define TMPOFF  (128 * ASTRIDE)        // 16896: tmp[256]
#define POSOFF  (TMPOFF + 256)         // pos[128]
#define SMEMFLOATS (POSOFF + 128)      // 17280 floats = 69120 B

__device__ float g_partial[256];

__device__ __forceinline__ uint32_t smem_u32(const void* p) {
    uint32_t a;
    asm("{ .reg .u64 t; cvta.to.shared.u64 t, %1; cvt.u32.u64 %0, t; }"
        : "=r"(a) : "l"(p));
    return a;
}
__device__ __forceinline__ uint32_t f2tf32(float f) {
    uint32_t u;
    asm("cvt.rna.tf32.f32 %0, %1;" : "=r"(u) : "f"(f));
    return u;
}
__device__ __forceinline__ void cp_async16(uint32_t dst, const void* src) {
    asm volatile("cp.async.ca.shared.global [%0], [%1], 16;"
                 :: "r"(dst), "l"(src) : "memory");
}
__device__ __forceinline__ void cp_commit() {
    asm volatile("cp.async.commit_group;" ::: "memory");
}
template <int N> __device__ __forceinline__ void cp_wait() {
    asm volatile("cp.async.wait_group %0;" :: "n"(N) : "memory");
}
__device__ __forceinline__ void mma_tf32(float& c0, float& c1, float& c2, float& c3,
                                         uint32_t a0, uint32_t a1, uint32_t a2, uint32_t a3,
                                         uint32_t b0, uint32_t b1) {
    asm volatile("mma.sync.aligned.m16n8k8.row.col.f32.tf32.tf32.f32 "
                 "{%0,%1,%2,%3}, {%4,%5,%6,%7}, {%8,%9}, {%0,%1,%2,%3};"
                 : "+f"(c0), "+f"(c1), "+f"(c2), "+f"(c3)
                 : "r"(a0), "r"(a1), "r"(a2), "r"(a3), "r"(b0), "r"(b1));
}

extern __shared__ float smf[];

__global__ void __launch_bounds__(THREADS, 2)
patchnce_main(const float* __restrict__ q,
              const float* __restrict__ p,
              const float* __restrict__ neg) {
    const int tid  = threadIdx.x;
    const int w    = tid >> 5;          // warp 0..7 -> rows 16w..16w+15
    const int lane = tid & 31;
    const int g    = lane >> 2;         // groupID 0..7
    const int t4   = lane & 3;
    const int b    = blockIdx.y;
    const int n0   = blockIdx.x * NTILE;

    float* Asm  = smf;                  // [128][ASTRIDE]  (staged Q tile, tf32)
    float* tmp  = smf + TMPOFF;         // [256]
    float* posv = smf + POSOFF;         // [128]

    // ---------------- Phase 1: stage Q tile (tf32) + positive dot ----------
    {
        const int r  = tid & 127;
        const int c0 = (tid >> 7) * 64;          // c-half 0 or 64
        const float* qb = q + (size_t)b * C_ * N_ + n0 + r;
        const float* pb = p + (size_t)b * C_ * N_ + n0 + r;
        float pd = 0.f;
#pragma unroll 8
        for (int c = c0; c < c0 + 64; c++) {
            float qv = qb[(size_t)c * N_];
            float pv = pb[(size_t)c * N_];
            pd = fmaf(qv, pv, pd);
            Asm[c * ASTRIDE + r] = __uint_as_float(f2tf32(qv));
        }
        tmp[tid] = pd;
    }
    __syncthreads();
    if (tid < 128) posv[tid] = tmp[tid] + tmp[tid + 128];

    // ---------------- Phase 2: A fragments -> 64 registers per thread ------
    uint32_t afr[64];
    {
        const int mrow = w * 16;
#pragma unroll
        for (int ks = 0; ks < 16; ks++) {
            const int k0 = ks * 8;
            afr[ks * 4 + 0] = __float_as_uint(Asm[(k0 + t4)     * ASTRIDE + mrow + g]);
            afr[ks * 4 + 1] = __float_as_uint(Asm[(k0 + t4)     * ASTRIDE + mrow + g + 8]);
            afr[ks * 4 + 2] = __float_as_uint(Asm[(k0 + t4 + 4) * ASTRIDE + mrow + g]);
            afr[ks * 4 + 3] = __float_as_uint(Asm[(k0 + t4 + 4) * ASTRIDE + mrow + g + 8]);
        }
    }
    __syncthreads();   // done reading A-stage; space becomes B double-buffer

    // ---------------- Phase 3: stream Neg chunks, HMMA + online softmax ----
    const float* nb = neg + (size_t)b * C_ * N_;
    const uint32_t bsm = smem_u32(smf);
    float rmax_lo = -1e30f, rsum_lo = 0.f;
    float rmax_hi = -1e30f, rsum_hi = 0.f;

    // per-thread copy coords: idx = tid + i*256; k = idx>>3, f = idx&7
    const int ck = tid >> 3;
    const int cf = tid & 7;

    auto issueB = [&](int ch) {
        const float* src = nb + ch * MCHUNK;
        const uint32_t dst = bsm + ((ch & 1) * BBUF) * 4;
#pragma unroll
        for (int i = 0; i < 4; i++) {
            const int k = ck + i * 32;
            cp_async16(dst + (k * BSTRIDE + cf * 4) * 4,
                       src + (size_t)k * N_ + cf * 4);
        }
        cp_commit();
    };

    issueB(0);
    for (int ch = 0; ch < NCHUNKS; ch++) {
        if (ch + 1 < NCHUNKS) { issueB(ch + 1); cp_wait<1>(); }
        else                  { cp_wait<0>(); }
        __syncthreads();

        const float* Bsm = smf + (ch & 1) * BBUF;
        float acc[4][4];
#pragma unroll
        for (int i = 0; i < 4; i++)
#pragma unroll
            for (int j = 0; j < 4; j++) acc[i][j] = 0.f;

#pragma unroll
        for (int ks = 0; ks < 16; ks++) {
            const int k0 = ks * 8;
#pragma unroll
            for (int grp = 0; grp < 4; grp++) {
                uint32_t b0 = f2tf32(Bsm[(k0 + t4)     * BSTRIDE + grp * 8 + g]);
                uint32_t b1 = f2tf32(Bsm[(k0 + t4 + 4) * BSTRIDE + grp * 8 + g]);
                mma_tf32(acc[grp][0], acc[grp][1], acc[grp][2], acc[grp][3],
                         afr[ks * 4 + 0], afr[ks * 4 + 1],
                         afr[ks * 4 + 2], afr[ks * 4 + 3], b0, b1);
            }
        }
        __syncthreads();

        // online softmax update: row_lo = vals acc[grp][0..1], row_hi = acc[grp][2..3]
        {
            float vm = -1e30f;
#pragma unroll
            for (int grp = 0; grp < 4; grp++)
                vm = fmaxf(vm, fmaxf(acc[grp][0], acc[grp][1]));
            float lm = vm * SCALE;
            if (lm > rmax_lo) { rsum_lo *= __expf(rmax_lo - lm); rmax_lo = lm; }
#pragma unroll
            for (int grp = 0; grp < 4; grp++) {
                rsum_lo += __expf(fmaf(acc[grp][0], SCALE, -rmax_lo));
                rsum_lo += __expf(fmaf(acc[grp][1], SCALE, -rmax_lo));
            }
        }
        {
            float vm = -1e30f;
#pragma unroll
            for (int grp = 0; grp < 4; grp++)
                vm = fmaxf(vm, fmaxf(acc[grp][2], acc[grp][3]));
            float lm = vm * SCALE;
            if (lm > rmax_hi) { rsum_hi *= __expf(rmax_hi - lm); rmax_hi = lm; }
#pragma unroll
            for (int grp = 0; grp < 4; grp++) {
                rsum_hi += __expf(fmaf(acc[grp][2], SCALE, -rmax_hi));
                rsum_hi += __expf(fmaf(acc[grp][3], SCALE, -rmax_hi));
            }
        }
    }

    // ---------------- Combine across the 4 lanes sharing each row ----------
#pragma unroll
    for (int d = 1; d <= 2; d <<= 1) {
        float om = __shfl_xor_sync(0xFFFFFFFFu, rmax_lo, d);
        float os = __shfl_xor_sync(0xFFFFFFFFu, rsum_lo, d);
        float nm = fmaxf(rmax_lo, om);
        rsum_lo = rsum_lo * __expf(rmax_lo - nm) + os * __expf(om - nm);
        rmax_lo = nm;
        om = __shfl_xor_sync(0xFFFFFFFFu, rmax_hi, d);
        os = __shfl_xor_sync(0xFFFFFFFFu, rsum_hi, d);
        nm = fmaxf(rmax_hi, om);
        rsum_hi = rsum_hi * __expf(rmax_hi - nm) + os * __expf(om - nm);
        rmax_hi = nm;
    }

    float loss = 0.f;
    if (t4 == 0) {
        const int r = w * 16 + g;
        {
            float lp = posv[r] * SCALE;
            float M2 = fmaxf(rmax_lo, lp);
            float S2 = rsum_lo * __expf(rmax_lo - M2) + __expf(lp - M2);
            loss += M2 + __logf(S2) - lp;
        }
        {
            float lp = posv[r + 8] * SCALE;
            float M2 = fmaxf(rmax_hi, lp);
            float S2 = rsum_hi * __expf(rmax_hi - M2) + __expf(lp - M2);
            loss += M2 + __logf(S2) - lp;
        }
    }

    // ---------------- Deterministic per-CTA reduction ----------------------
    __syncthreads();
    tmp[tid] = loss;
    __syncthreads();
    for (int o = 128; o > 0; o >>= 1) {
        if (tid < o) tmp[tid] += tmp[tid + o];
        __syncthreads();
    }
    if (tid == 0) g_partial[blockIdx.y * 16 + blockIdx.x] = tmp[0];
}

// ---------------------------------------------------------------------------
__global__ void final_kernel(float* __restrict__ out) {
    __shared__ float red[256];
    int t = threadIdx.x;
    red[t] = g_partial[t];
    __syncthreads();
    for (int off = 128; off > 0; off >>= 1) {
        if (t < off) red[t] += red[t + off];
        __syncthreads();
    }
    if (t == 0) out[0] = red[0] / (float)(B_ * N_);
}

// ---------------------------------------------------------------------------
extern "C" void kernel_launch(void* const* d_in, const int* in_sizes, int n_in,
                              void* d_out, int out_size) {
    const float* q   = (const float*)d_in[0];
    const float* pos = (const float*)d_in[1];
    const float* neg = (const float*)d_in[2];
    float* out = (float*)d_out;

    cudaFuncSetAttribute(patchnce_main,
                         cudaFuncAttributeMaxDynamicSharedMemorySize,
                         SMEMFLOATS * sizeof(float));
    patchnce_main<<<dim3(16, 16), THREADS, SMEMFLOATS * sizeof(float)>>>(q, pos, neg);
    final_kernel<<<1, 256>>>(out);
}

// round 5
// speedup vs baseline: 5.3387x; 1.8853x over previous
#include <cuda_runtime.h>
#include <cuda_fp16.h>
#include <cstdint>

// Problem constants: B=16, C=128, N=M=2048
#define B_  16
#define C_  128
#define N_  2048
#define SCALE 10.0f

#define NTILE   128
#define MCHUNK  32
#define NCHUNKS 64
#define THREADS 256

// SMEM (uint32 units). A-stage (f16x2 k-pairs) overlaps B buffer in time.
#define APAD 132                 // A stage: [64 kpair][APAD] u32
#define BP   40                  // B buffer: [64 kpair][BP] u32 (conflict-free frags)
#define TMPU (64 * APAD)         // tmp[256] floats
#define POSU (TMPU + 256)        // posv[128] floats
#define FLGU (POSU + 128)        // flag
#define SMEMU (FLGU + 4)

__device__ float g_partial[256];
__device__ unsigned int g_count;   // zero-init; reset by last CTA each run

__device__ __forceinline__ void mma_f16(float& c0, float& c1, float& c2, float& c3,
                                        const uint32_t* a, uint32_t b0, uint32_t b1) {
    asm volatile("mma.sync.aligned.m16n8k16.row.col.f32.f16.f16.f32 "
                 "{%0,%1,%2,%3}, {%4,%5,%6,%7}, {%8,%9}, {%0,%1,%2,%3};"
                 : "+f"(c0), "+f"(c1), "+f"(c2), "+f"(c3)
                 : "r"(a[0]), "r"(a[1]), "r"(a[2]), "r"(a[3]), "r"(b0), "r"(b1));
}

extern __shared__ uint32_t smu[];

__global__ void __launch_bounds__(THREADS, 2)
patchnce_main(const float* __restrict__ q,
              const float* __restrict__ p,
              const float* __restrict__ neg,
              float* __restrict__ out) {
    const int tid  = threadIdx.x;
    const int w    = tid >> 5;
    const int lane = tid & 31;
    const int g    = lane >> 2;
    const int t4   = lane & 3;
    const int b    = blockIdx.y;
    const int n0   = blockIdx.x * NTILE;

    float* tmp  = (float*)&smu[TMPU];
    float* posv = (float*)&smu[POSU];
    int*   flag = (int*)&smu[FLGU];

    // ------------- Phase 1: stage Q tile as f16x2 k-pairs + positive dot ----
    {
        const int m  = tid & 127;
        const int kh = tid >> 7;                 // k-half
        const float* qb = q + (size_t)b * C_ * N_ + n0 + m;
        const float* pb = p + (size_t)b * C_ * N_ + n0 + m;
        float pd = 0.f;
#pragma unroll 8
        for (int kp = kh * 32; kp < kh * 32 + 32; kp++) {
            float q0 = qb[(size_t)(2 * kp)     * N_];
            float q1 = qb[(size_t)(2 * kp + 1) * N_];
            float p0 = pb[(size_t)(2 * kp)     * N_];
            float p1 = pb[(size_t)(2 * kp + 1) * N_];
            pd = fmaf(q0, p0, fmaf(q1, p1, pd));
            __half2 h = __floats2half2_rn(q0, q1);    // lo = k even
            smu[kp * APAD + m] = *(uint32_t*)&h;
        }
        tmp[tid] = pd;
    }
    __syncthreads();
    if (tid < 128) posv[tid] = tmp[tid] + tmp[tid + 128];

    // ------------- Phase 2: A fragments -> 32 registers ---------------------
    uint32_t afr[32];
    {
        const int mrow = w * 16 + g;
#pragma unroll
        for (int ks = 0; ks < 8; ks++) {
            afr[ks * 4 + 0] = smu[(ks * 8 + t4)     * APAD + mrow];
            afr[ks * 4 + 1] = smu[(ks * 8 + t4)     * APAD + mrow + 8];
            afr[ks * 4 + 2] = smu[(ks * 8 + t4 + 4) * APAD + mrow];
            afr[ks * 4 + 3] = smu[(ks * 8 + t4 + 4) * APAD + mrow + 8];
        }
    }
    __syncthreads();   // A-stage region becomes the B buffer

    // ------------- Phase 3: stream Neg, fp16 HMMA + online softmax ----------
    const float* nb = neg + (size_t)b * C_ * N_;
    const int kp0 = tid >> 3;          // 0..31 (task kp; second task kp0+32)
    const int mq  = tid & 7;           // m-quad

    float4 pr[4];                      // register prefetch: 2 tasks x 2 k-rows
    auto loadB = [&](int ch) {
        const float* s = nb + ch * MCHUNK + mq * 4;
#pragma unroll
        for (int i = 0; i < 2; i++) {
            const int kp = kp0 + i * 32;
            pr[i * 2 + 0] = *(const float4*)(s + (size_t)(2 * kp)     * N_);
            pr[i * 2 + 1] = *(const float4*)(s + (size_t)(2 * kp + 1) * N_);
        }
    };
    auto storeB = [&]() {
#pragma unroll
        for (int i = 0; i < 2; i++) {
            const int kp = kp0 + i * 32;
            __half2 h0 = __floats2half2_rn(pr[i*2].x, pr[i*2+1].x);
            __half2 h1 = __floats2half2_rn(pr[i*2].y, pr[i*2+1].y);
            __half2 h2 = __floats2half2_rn(pr[i*2].z, pr[i*2+1].z);
            __half2 h3 = __floats2half2_rn(pr[i*2].w, pr[i*2+1].w);
            uint4 v = { *(uint32_t*)&h0, *(uint32_t*)&h1,
                        *(uint32_t*)&h2, *(uint32_t*)&h3 };
            *(uint4*)&smu[kp * BP + mq * 4] = v;
        }
    };

    float rmax_lo = -1e30f, rsum_lo = 0.f;
    float rmax_hi = -1e30f, rsum_hi = 0.f;

    loadB(0);
    for (int ch = 0; ch < NCHUNKS; ch++) {
        storeB();
        if (ch + 1 < NCHUNKS) loadB(ch + 1);   // prefetch; latency hidden by MMA
        __syncthreads();

        float acc[4][4];
#pragma unroll
        for (int i = 0; i < 4; i++)
#pragma unroll
            for (int j = 0; j < 4; j++) acc[i][j] = 0.f;

#pragma unroll
        for (int ks = 0; ks < 8; ks++) {
#pragma unroll
            for (int grp = 0; grp < 4; grp++) {
                uint32_t b0 = smu[(ks * 8 + t4)     * BP + grp * 8 + g];
                uint32_t b1 = smu[(ks * 8 + t4 + 4) * BP + grp * 8 + g];
                mma_f16(acc[grp][0], acc[grp][1], acc[grp][2], acc[grp][3],
                        afr + ks * 4, b0, b1);
            }
        }

        // online softmax: rows w*16+g (acc[.][0,1]) and w*16+g+8 (acc[.][2,3])
        {
            float vm = -1e30f;
#pragma unroll
            for (int grp = 0; grp < 4; grp++)
                vm = fmaxf(vm, fmaxf(acc[grp][0], acc[grp][1]));
            float lm = vm * SCALE;
            if (lm > rmax_lo) { rsum_lo *= __expf(rmax_lo - lm); rmax_lo = lm; }
#pragma unroll
            for (int grp = 0; grp < 4; grp++) {
                rsum_lo += __expf(fmaf(acc[grp][0], SCALE, -rmax_lo));
                rsum_lo += __expf(fmaf(acc[grp][1], SCALE, -rmax_lo));
            }
        }
        {
            float vm = -1e30f;
#pragma unroll
            for (int grp = 0; grp < 4; grp++)
                vm = fmaxf(vm, fmaxf(acc[grp][2], acc[grp][3]));
            float lm = vm * SCALE;
            if (lm > rmax_hi) { rsum_hi *= __expf(rmax_hi - lm); rmax_hi = lm; }
#pragma unroll
            for (int grp = 0; grp < 4; grp++) {
                rsum_hi += __expf(fmaf(acc[grp][2], SCALE, -rmax_hi));
                rsum_hi += __expf(fmaf(acc[grp][3], SCALE, -rmax_hi));
            }
        }
        __syncthreads();   // all reads done before next storeB
    }

    // ------------- Combine the 4 lanes sharing each row ---------------------
#pragma unroll
    for (int d = 1; d <= 2; d <<= 1) {
        float om = __shfl_xor_sync(0xFFFFFFFFu, rmax_lo, d);
        float os = __shfl_xor_sync(0xFFFFFFFFu, rsum_lo, d);
        float nm = fmaxf(rmax_lo, om);
        rsum_lo = rsum_lo * __expf(rmax_lo - nm) + os * __expf(om - nm);
        rmax_lo = nm;
        om = __shfl_xor_sync(0xFFFFFFFFu, rmax_hi, d);
        os = __shfl_xor_sync(0xFFFFFFFFu, rsum_hi, d);
        nm = fmaxf(rmax_hi, om);
        rsum_hi = rsum_hi * __expf(rmax_hi - nm) + os * __expf(om - nm);
        rmax_hi = nm;
    }

    float loss = 0.f;
    if (t4 == 0) {
        const int r = w * 16 + g;
        {
            float lp = posv[r] * SCALE;
            float M2 = fmaxf(rmax_lo, lp);
            float S2 = rsum_lo * __expf(rmax_lo - M2) + __expf(lp - M2);
            loss += M2 + __logf(S2) - lp;
        }
        {
            float lp = posv[r + 8] * SCALE;
            float M2 = fmaxf(rmax_hi, lp);
            float S2 = rsum_hi * __expf(rmax_hi - M2) + __expf(lp - M2);
            loss += M2 + __logf(S2) - lp;
        }
    }

    // ------------- Deterministic per-CTA reduction --------------------------
    __syncthreads();
    tmp[tid] = loss;
    __syncthreads();
    for (int o = 128; o > 0; o >>= 1) {
        if (tid < o) tmp[tid] += tmp[tid + o];
        __syncthreads();
    }

    // ------------- Cross-CTA fold: last CTA finishes ------------------------
    const int cta = blockIdx.y * 16 + blockIdx.x;
    if (tid == 0) {
        g_partial[cta] = tmp[0];
        __threadfence();
        unsigned v = atomicAdd(&g_count, 1u);
        *flag = (v == 255u) ? 1 : 0;
    }
    __syncthreads();
    if (*flag) {
        __threadfence();                         // acquire partials
        tmp[tid] = g_partial[tid];
        __syncthreads();
        for (int o = 128; o > 0; o >>= 1) {
            if (tid < o) tmp[tid] += tmp[tid + o];
            __syncthreads();
        }
        if (tid == 0) {
            out[0] = tmp[0] / (float)(B_ * N_);
            g_count = 0;                         // reset for next replay
        }
    }
}

// ---------------------------------------------------------------------------
extern "C" void kernel_launch(void* const* d_in, const int* in_sizes, int n_in,
                              void* d_out, int out_size) {
    const float* q   = (const float*)d_in[0];
    const float* pos = (const float*)d_in[1];
    const float* neg = (const float*)d_in[2];
    float* out = (float*)d_out;

    cudaFuncSetAttribute(patchnce_main,
                         cudaFuncAttributeMaxDynamicSharedMemorySize,
                         SMEMU * sizeof(uint32_t));
    patchnce_main<<<dim3(16, 16), THREADS, SMEMU * sizeof(uint32_t)>>>(q, pos, neg, out);
}